// round 1
// baseline (speedup 1.0000x reference)
#include <cuda_runtime.h>
#include <math.h>

// ---------------- problem constants ----------------
#define L_SEQ   2048
#define D_MODEL 1024
#define D_INNER 2048
#define D_STATE 16
#define DT_RANK 64
#define D_CONV  4

// ---------------- scratch (no allocations allowed) ----------------
__device__ float g_u0[L_SEQ * D_INNER];     // in-proj output (pre-conv)
__device__ float g_gate[L_SEQ * D_INNER];   // gate-proj output (pre-silu)
__device__ float g_u[L_SEQ * D_INNER];      // post conv+silu
__device__ float g_t[L_SEQ * DT_RANK];      // dt low-rank
__device__ float g_delta[L_SEQ * D_INNER];  // softplus dt
__device__ float g_y[L_SEQ * D_INNER];      // pre out-proj

// ---------------- generic 128x128 SIMT fp32 GEMM ----------------
// C[M,N] = A[M,K] @ B[K,N] + bias[N], optional softplus epilogue.
// Requires: M % 128 == 0, N % 128 == 0, K % 8 == 0.
#define BM 128
#define BN 128
#define BK 8
#define TM 8
#define TN 8

__global__ __launch_bounds__(256, 2)
void gemm128(const float* __restrict__ A, const float* __restrict__ B,
             const float* __restrict__ bias, float* __restrict__ C,
             int M, int N, int K, int epilogue /*0: bias, 1: bias+softplus*/) {
    __shared__ float As[BK][BM];   // transposed A tile
    __shared__ float Bs[BK][BN];

    const int bx = blockIdx.x;     // N tiles
    const int by = blockIdx.y;     // M tiles
    const int tid = threadIdx.x;

    const float* Ab = A + (size_t)by * BM * K;
    const float* Bb = B + (size_t)bx * BN;

    // A tile load: 128x8 floats -> 1 float4 per thread
    const int arow  = tid >> 1;          // 0..127
    const int acol4 = (tid & 1) * 4;     // 0 or 4
    // B tile load: 8x128 floats -> 1 float4 per thread
    const int brow  = tid >> 5;          // 0..7
    const int bcol4 = (tid & 31) * 4;    // 0..124

    const int tr = tid >> 4;             // 0..15
    const int tc = tid & 15;             // 0..15

    float acc[TM][TN];
    #pragma unroll
    for (int i = 0; i < TM; i++)
        #pragma unroll
        for (int j = 0; j < TN; j++) acc[i][j] = 0.f;

    for (int k0 = 0; k0 < K; k0 += BK) {
        float4 a4 = *(const float4*)(Ab + (size_t)arow * K + k0 + acol4);
        As[acol4 + 0][arow] = a4.x;
        As[acol4 + 1][arow] = a4.y;
        As[acol4 + 2][arow] = a4.z;
        As[acol4 + 3][arow] = a4.w;
        float4 b4 = *(const float4*)(Bb + (size_t)(k0 + brow) * N + bcol4);
        *(float4*)&Bs[brow][bcol4] = b4;
        __syncthreads();

        #pragma unroll
        for (int kk = 0; kk < BK; kk++) {
            float ar[TM], br[TN];
            #pragma unroll
            for (int i = 0; i < TM; i++) ar[i] = As[kk][tr * TM + i];
            #pragma unroll
            for (int j = 0; j < TN; j++) br[j] = Bs[kk][tc * TN + j];
            #pragma unroll
            for (int i = 0; i < TM; i++)
                #pragma unroll
                for (int j = 0; j < TN; j++)
                    acc[i][j] = fmaf(ar[i], br[j], acc[i][j]);
        }
        __syncthreads();
    }

    // epilogue + store (vectorized by 4 along N)
    #pragma unroll
    for (int i = 0; i < TM; i++) {
        int row = by * BM + tr * TM + i;
        #pragma unroll
        for (int j4 = 0; j4 < TN; j4 += 4) {
            int col = bx * BN + tc * TN + j4;
            float4 v;
            float* vp = &v.x;
            #pragma unroll
            for (int j = 0; j < 4; j++) {
                float t = acc[i][j4 + j] + bias[col + j];
                if (epilogue == 1) {
                    // softplus
                    t = (t > 20.f) ? t : log1pf(expf(t));
                }
                vp[j] = t;
            }
            *(float4*)(C + (size_t)row * N + col) = v;
        }
    }
}

// ---------------- small GEMM for dt1: M=2048, N=64, K=2048 ----------------
__global__ __launch_bounds__(256)
void gemm_n64(const float* __restrict__ A, const float* __restrict__ B,
              const float* __restrict__ bias, float* __restrict__ C, int K) {
    // block: 256 threads = 4 rows x 64 cols
    const int m = blockIdx.x * 4 + (threadIdx.x >> 6);
    const int n = threadIdx.x & 63;
    const float* Ar = A + (size_t)m * K;
    float acc = 0.f;
    #pragma unroll 4
    for (int k = 0; k < K; k += 4) {
        float a0 = Ar[k + 0], a1 = Ar[k + 1], a2 = Ar[k + 2], a3 = Ar[k + 3];
        acc = fmaf(a0, B[(k + 0) * 64 + n], acc);
        acc = fmaf(a1, B[(k + 1) * 64 + n], acc);
        acc = fmaf(a2, B[(k + 2) * 64 + n], acc);
        acc = fmaf(a3, B[(k + 3) * 64 + n], acc);
    }
    C[(size_t)m * 64 + n] = acc + bias[n];
}

// ---------------- causal depthwise conv (width 4) + SiLU ----------------
__global__ __launch_bounds__(256)
void conv_silu(const float* __restrict__ U0, const float* __restrict__ cw,
               const float* __restrict__ cb, float* __restrict__ U) {
    int idx = blockIdx.x * blockDim.x + threadIdx.x;
    if (idx >= L_SEQ * D_INNER) return;
    int d = idx & (D_INNER - 1);
    int l = idx >> 11;   // D_INNER = 2048 = 2^11
    float w0 = cw[d * 4 + 0], w1 = cw[d * 4 + 1], w2 = cw[d * 4 + 2], w3 = cw[d * 4 + 3];
    float acc = cb[d] + w3 * U0[idx];
    if (l >= 1) acc = fmaf(w2, U0[idx - D_INNER], acc);
    if (l >= 2) acc = fmaf(w1, U0[idx - 2 * D_INNER], acc);
    if (l >= 3) acc = fmaf(w0, U0[idx - 3 * D_INNER], acc);
    // silu
    U[idx] = acc / (1.f + expf(-acc));
}

// ---------------- SSM sequential scan + gating ----------------
// One thread per (d, n). 16 lanes per channel, 16 channels per 256-thread block.
__global__ __launch_bounds__(256)
void scan_kernel(const float* __restrict__ delta, const float* __restrict__ u,
                 const float* __restrict__ gpre,
                 const float* __restrict__ A_log, const float* __restrict__ Bm,
                 const float* __restrict__ Cm, const float* __restrict__ Dv,
                 float* __restrict__ Y) {
    const int tid  = threadIdx.x;
    const int lane = tid & 15;                 // n
    const int grp  = tid >> 4;                 // channel within block
    const int d    = blockIdx.x * 16 + grp;

    const float A  = -expf(A_log[lane]);
    const float Bn = Bm[lane * D_INNER + d];
    const float Cn = Cm[lane * D_INNER + d];
    const float Dd = Dv[d];
    const bool  smallA = fabsf(A) < 1e-6f;
    const float invA   = smallA ? 0.f : 1.f / A;

    float h = 0.f;
    int idx = d;
    // prefetch first element
    float dt = delta[idx];
    float uu = u[idx];
    float gg = gpre[idx];

    for (int l = 0; l < L_SEQ; l++) {
        float dtc = dt, uuc = uu, ggc = gg;
        int nidx = idx + D_INNER;
        if (l + 1 < L_SEQ) {   // prefetch next step
            dt = delta[nidx];
            uu = u[nidx];
            gg = gpre[nidx];
        }
        float dA = dtc * A;
        float ab = __expf(dA);
        float ex = smallA ? dtc * (1.f + 0.5f * dA) : (ab - 1.f) * invA;
        h = fmaf(ab, h, ex * Bn * uuc);
        float c = h * Cn;
        c += __shfl_xor_sync(0xffffffffu, c, 1);
        c += __shfl_xor_sync(0xffffffffu, c, 2);
        c += __shfl_xor_sync(0xffffffffu, c, 4);
        c += __shfl_xor_sync(0xffffffffu, c, 8);
        if (lane == 0) {
            float sil = ggc / (1.f + expf(-ggc));   // silu(gate)
            Y[idx] = (c + Dd * uuc) * sil;
        }
        idx = nidx;
    }
}

// ---------------- launcher ----------------
extern "C" void kernel_launch(void* const* d_in, const int* in_sizes, int n_in,
                              void* d_out, int out_size) {
    const float* x      = (const float*)d_in[0];
    const float* in_w   = (const float*)d_in[1];
    const float* in_b   = (const float*)d_in[2];
    const float* conv_w = (const float*)d_in[3];
    const float* conv_b = (const float*)d_in[4];
    const float* A_log  = (const float*)d_in[5];
    const float* B_mat  = (const float*)d_in[6];
    const float* C_mat  = (const float*)d_in[7];
    const float* D_vec  = (const float*)d_in[8];
    const float* gate_w = (const float*)d_in[9];
    const float* gate_b = (const float*)d_in[10];
    const float* dt1_w  = (const float*)d_in[11];
    const float* dt1_b  = (const float*)d_in[12];
    const float* dt2_w  = (const float*)d_in[13];
    const float* dt2_b  = (const float*)d_in[14];
    const float* out_w  = (const float*)d_in[15];
    const float* out_b  = (const float*)d_in[16];
    float* out = (float*)d_out;

    float *u0, *gate, *u, *t, *delta, *y;
    cudaGetSymbolAddress((void**)&u0,    g_u0);
    cudaGetSymbolAddress((void**)&gate,  g_gate);
    cudaGetSymbolAddress((void**)&u,     g_u);
    cudaGetSymbolAddress((void**)&t,     g_t);
    cudaGetSymbolAddress((void**)&delta, g_delta);
    cudaGetSymbolAddress((void**)&y,     g_y);

    // 1) in-proj: u0 = x @ in_w + in_b          (2048 x 2048, K=1024)
    gemm128<<<dim3(D_INNER / BN, L_SEQ / BM), 256>>>(x, in_w, in_b, u0,
                                                     L_SEQ, D_INNER, D_MODEL, 0);
    // 2) gate-proj: gate = x @ gate_w + gate_b
    gemm128<<<dim3(D_INNER / BN, L_SEQ / BM), 256>>>(x, gate_w, gate_b, gate,
                                                     L_SEQ, D_INNER, D_MODEL, 0);
    // 3) conv + silu
    conv_silu<<<(L_SEQ * D_INNER) / 256, 256>>>(u0, conv_w, conv_b, u);
    // 4) dt low-rank: t = u @ dt1_w + dt1_b     (2048 x 64, K=2048)
    gemm_n64<<<L_SEQ / 4, 256>>>(u, dt1_w, dt1_b, t, D_INNER);
    // 5) delta = softplus(t @ dt2_w + dt2_b)    (2048 x 2048, K=64)
    gemm128<<<dim3(D_INNER / BN, L_SEQ / BM), 256>>>(t, dt2_w, dt2_b, delta,
                                                     L_SEQ, D_INNER, DT_RANK, 1);
    // 6) SSM scan + D skip + gating -> y
    scan_kernel<<<D_INNER / 16, 256>>>(delta, u, gate, A_log, B_mat, C_mat, D_vec, y);
    // 7) out-proj: out = y @ out_w + out_b      (2048 x 1024, K=2048)
    gemm128<<<dim3(D_MODEL / BN, L_SEQ / BM), 256>>>(y, out_w, out_b, out,
                                                     L_SEQ, D_MODEL, D_INNER, 0);
}

// round 3
// speedup vs baseline: 2.6561x; 2.6561x over previous
#include <cuda_runtime.h>
#include <cuda_bf16.h>
#include <math.h>

// ---------------- problem constants ----------------
#define L_SEQ   2048
#define D_MODEL 1024
#define D_INNER 2048
#define DT_RANK 64
#define NCHUNK  16
#define CHUNK   128

typedef __nv_bfloat16 bf16;
typedef __nv_bfloat162 bf162;

// ---------------- scratch (no allocations allowed) ----------------
__device__ float g_u0[L_SEQ * D_INNER];
__device__ float g_gate[L_SEQ * D_INNER];
__device__ float g_u[L_SEQ * D_INNER];
__device__ float g_t[L_SEQ * DT_RANK];
__device__ float g_delta[L_SEQ * D_INNER];
__device__ float g_y[L_SEQ * D_INNER];

// split bf16 activations A' = [Ah | Al | Ah]  (M x 3K)
__device__ bf16 g_xA[L_SEQ * 3 * D_MODEL];
__device__ bf16 g_uA[L_SEQ * 3 * D_INNER];
__device__ bf16 g_tA[L_SEQ * 3 * DT_RANK];
__device__ bf16 g_yA[L_SEQ * 3 * D_INNER];

// split bf16 weights B' = [Bh ; Bh ; Bl]  (3K x ldb)
__device__ bf16 g_inB[3 * D_MODEL * D_INNER];
__device__ bf16 g_gateB[3 * D_MODEL * D_INNER];
__device__ bf16 g_dt1B[3 * D_INNER * 128];      // N padded 64 -> 128
__device__ bf16 g_dt2B[3 * DT_RANK * D_INNER];
__device__ bf16 g_outB[3 * D_INNER * D_MODEL];

// chunked scan state
__device__ float g_hS[NCHUNK * D_INNER * 16];
__device__ float g_pS[NCHUNK * D_INNER * 16];
__device__ float g_hin[NCHUNK * D_INNER * 16];

// ---------------- helpers ----------------
__device__ __forceinline__ unsigned smem_u32(const void* p) {
    unsigned a;
    asm("{ .reg .u64 t; cvta.to.shared.u64 t, %1; cvt.u32.u64 %0, t; }"
        : "=r"(a) : "l"(p));
    return a;
}

__device__ __forceinline__ void cp16(unsigned saddr, const void* g) {
    asm volatile("cp.async.cg.shared.global [%0], [%1], 16;"
                 :: "r"(saddr), "l"(g));
}
#define CP_COMMIT() asm volatile("cp.async.commit_group;" ::: "memory")
#define CP_WAIT(n)  asm volatile("cp.async.wait_group %0;" :: "n"(n) : "memory")

#define LDSM_X4(r, addr) \
    asm volatile("ldmatrix.sync.aligned.m8n8.x4.shared.b16 {%0,%1,%2,%3}, [%4];" \
        : "=r"((r)[0]), "=r"((r)[1]), "=r"((r)[2]), "=r"((r)[3]) : "r"(addr))

#define LDSM_X4_T(r, addr) \
    asm volatile("ldmatrix.sync.aligned.m8n8.x4.trans.shared.b16 {%0,%1,%2,%3}, [%4];" \
        : "=r"((r)[0]), "=r"((r)[1]), "=r"((r)[2]), "=r"((r)[3]) : "r"(addr))

#define MMA16816(d, a, b0, b1) \
    asm volatile("mma.sync.aligned.m16n8k16.row.col.f32.bf16.bf16.f32 " \
        "{%0,%1,%2,%3}, {%4,%5,%6,%7}, {%8,%9}, {%0,%1,%2,%3};" \
        : "+f"((d)[0]), "+f"((d)[1]), "+f"((d)[2]), "+f"((d)[3]) \
        : "r"((a)[0]), "r"((a)[1]), "r"((a)[2]), "r"((a)[3]), "r"(b0), "r"(b1))

// ---------------- bf16 HMMA GEMM: C[M,N] = A'[M,Kp] @ B'[Kp,N] ----------------
// tile 128x128, 8 warps (each 32x64), K chunk = 64 bf16, 2-stage cp.async.
// smem/stage: A 128x64 bf16 (16KB, 128B rows, 16B-chunk XOR swizzle)
//             B 64x128 bf16 (16KB, 256B rows, same swizzle)
#define TG_SMEM 65536

__global__ __launch_bounds__(256, 2)
void tgemm(const bf16* __restrict__ A, const bf16* __restrict__ B,
           const float* __restrict__ bias, float* __restrict__ C,
           int Kp, int ldb, int ldc, int Nvalid, int softplus_ep)
{
    extern __shared__ char smem[];
    const unsigned sb = smem_u32(smem);
    const int tid  = threadIdx.x;
    const int wid  = tid >> 5;
    const int lane = tid & 31;
    const int m0 = blockIdx.y * 128;
    const int n0 = blockIdx.x * 128;
    const int warp_m = (wid & 3) * 32;
    const int warp_n = (wid >> 2) * 64;

    float acc[2][8][4];
    #pragma unroll
    for (int i = 0; i < 2; i++)
        #pragma unroll
        for (int j = 0; j < 8; j++)
            #pragma unroll
            for (int q = 0; q < 4; q++) acc[i][j][q] = 0.f;

    const int nc = Kp >> 6;

    // tile load: idx over A(1024 16B-chunks) + B(1024 16B-chunks), 256 threads x 4+4
    auto load_stage = [&](int c, int s) {
        unsigned st = sb + (unsigned)s * 32768u;
        int k0 = c << 6;
        #pragma unroll
        for (int i = 0; i < 4; i++) {
            int idx = i * 256 + tid;
            int r  = idx >> 3;          // 0..127
            int ch = idx & 7;           // 0..7
            cp16(st + (unsigned)(r * 128 + ((ch ^ (r & 7)) << 4)),
                 A + (size_t)(m0 + r) * Kp + k0 + ch * 8);
        }
        #pragma unroll
        for (int i = 0; i < 4; i++) {
            int idx = i * 256 + tid;
            int k  = idx >> 4;          // 0..63
            int ch = idx & 15;          // 0..15
            cp16(st + 16384u + (unsigned)(k * 256 + ((ch ^ (k & 7)) << 4)),
                 B + (size_t)(k0 + k) * ldb + n0 + ch * 8);
        }
    };

    load_stage(0, 0);
    CP_COMMIT();

    for (int c = 0; c < nc; c++) {
        if (c + 1 < nc) {
            load_stage(c + 1, (c + 1) & 1);
            CP_COMMIT();
            CP_WAIT(1);
        } else {
            CP_WAIT(0);
        }
        __syncthreads();

        unsigned sA = sb + (unsigned)(c & 1) * 32768u;
        unsigned sB = sA + 16384u;

        #pragma unroll
        for (int ks = 0; ks < 4; ks++) {
            unsigned af[2][4];
            #pragma unroll
            for (int mi = 0; mi < 2; mi++) {
                int m  = warp_m + mi * 16 + (lane & 15);
                int ch = ks * 2 + (lane >> 4);
                LDSM_X4(af[mi], sA + (unsigned)(m * 128 + ((ch ^ (m & 7)) << 4)));
            }
            unsigned bfg[4][4];
            #pragma unroll
            for (int nj2 = 0; nj2 < 4; nj2++) {
                int k  = ks * 16 + (lane & 15);
                int ch = ((warp_n + nj2 * 16) >> 3) + (lane >> 4);
                LDSM_X4_T(bfg[nj2], sB + (unsigned)(k * 256 + ((ch ^ (k & 7)) << 4)));
            }
            #pragma unroll
            for (int mi = 0; mi < 2; mi++)
                #pragma unroll
                for (int nj = 0; nj < 8; nj++)
                    MMA16816(acc[mi][nj], af[mi],
                             bfg[nj >> 1][(nj & 1) * 2], bfg[nj >> 1][(nj & 1) * 2 + 1]);
        }
        __syncthreads();
    }

    // epilogue: direct float2 stores
    #pragma unroll
    for (int mi = 0; mi < 2; mi++) {
        int r = m0 + warp_m + mi * 16 + (lane >> 2);
        #pragma unroll
        for (int nj = 0; nj < 8; nj++) {
            int col = warp_n + nj * 8 + (lane & 3) * 2;
            if (col < Nvalid) {
                float b0 = bias[col], b1 = bias[col + 1];
                float v0 = acc[mi][nj][0] + b0, v1 = acc[mi][nj][1] + b1;
                float v2 = acc[mi][nj][2] + b0, v3 = acc[mi][nj][3] + b1;
                if (softplus_ep) {
                    v0 = (v0 > 20.f) ? v0 : log1pf(expf(v0));
                    v1 = (v1 > 20.f) ? v1 : log1pf(expf(v1));
                    v2 = (v2 > 20.f) ? v2 : log1pf(expf(v2));
                    v3 = (v3 > 20.f) ? v3 : log1pf(expf(v3));
                }
                *(float2*)(C + (size_t)r * ldc + n0 + col)       = make_float2(v0, v1);
                *(float2*)(C + (size_t)(r + 8) * ldc + n0 + col) = make_float2(v2, v3);
            }
        }
    }
}

// ---------------- split kernels ----------------
__device__ __forceinline__ void split1(float v, bf16& h, bf16& l) {
    h = __float2bfloat16_rn(v);
    l = __float2bfloat16_rn(v - __bfloat162float(h));
}

// activations: V[M,K] fp32 -> O[M,3K] bf16 = [hi | lo | hi]
__global__ __launch_bounds__(256)
void split_act(const float4* __restrict__ V, bf16* __restrict__ O,
               int K4, int K, int total4)
{
    int i = blockIdx.x * 256 + threadIdx.x;
    if (i >= total4) return;
    int m = i / K4;
    int k = (i - m * K4) * 4;
    float4 v = V[i];
    bf16 h0, l0, h1, l1, h2, l2, h3, l3;
    split1(v.x, h0, l0); split1(v.y, h1, l1);
    split1(v.z, h2, l2); split1(v.w, h3, l3);
    bf162 hi01 = {h0, h1}, hi23 = {h2, h3};
    bf162 lo01 = {l0, l1}, lo23 = {l2, l3};
    bf162* p0 = (bf162*)(O + (size_t)m * 3 * K + k);
    bf162* p1 = (bf162*)(O + (size_t)m * 3 * K + K + k);
    bf162* p2 = (bf162*)(O + (size_t)m * 3 * K + 2 * K + k);
    p0[0] = hi01; p0[1] = hi23;
    p1[0] = lo01; p1[1] = lo23;
    p2[0] = hi01; p2[1] = hi23;
}

// weights: W[K,N] fp32 -> O[3K, ldb] bf16 rows = [hi ; hi ; lo]
__global__ __launch_bounds__(256)
void split_w(const float4* __restrict__ W, bf16* __restrict__ O,
             int N4, int N, int ldb, int K, int total4)
{
    int i = blockIdx.x * 256 + threadIdx.x;
    if (i >= total4) return;
    int k = i / N4;
    int n = (i - k * N4) * 4;
    float4 v = ((const float4*)W)[i];
    bf16 h0, l0, h1, l1, h2, l2, h3, l3;
    split1(v.x, h0, l0); split1(v.y, h1, l1);
    split1(v.z, h2, l2); split1(v.w, h3, l3);
    bf162 hi01 = {h0, h1}, hi23 = {h2, h3};
    bf162 lo01 = {l0, l1}, lo23 = {l2, l3};
    bf162* p0 = (bf162*)(O + (size_t)k * ldb + n);
    bf162* p1 = (bf162*)(O + (size_t)(K + k) * ldb + n);
    bf162* p2 = (bf162*)(O + (size_t)(2 * K + k) * ldb + n);
    p0[0] = hi01; p0[1] = hi23;
    p1[0] = hi01; p1[1] = hi23;
    p2[0] = lo01; p2[1] = lo23;
}

// zero pad cols [64,128) of dt1B rows
__global__ __launch_bounds__(256)
void pad_dt1(bf16* __restrict__ O)
{
    int i = blockIdx.x * 256 + threadIdx.x;   // over 3*2048 * 32 (bf162 units)
    int row = i >> 5;
    int c2  = (i & 31) * 2;
    ((bf162*)(O + (size_t)row * 128 + 64 + c2))[0] = bf162{(bf16)0.f, (bf16)0.f};
}

// ---------------- causal depthwise conv (width 4) + SiLU ----------------
__global__ __launch_bounds__(256)
void conv_silu(const float* __restrict__ U0, const float* __restrict__ cw,
               const float* __restrict__ cb, float* __restrict__ U)
{
    int idx = blockIdx.x * blockDim.x + threadIdx.x;
    if (idx >= L_SEQ * D_INNER) return;
    int d = idx & (D_INNER - 1);
    int l = idx >> 11;
    float w0 = cw[d * 4 + 0], w1 = cw[d * 4 + 1], w2 = cw[d * 4 + 2], w3 = cw[d * 4 + 3];
    float acc = cb[d] + w3 * U0[idx];
    if (l >= 1) acc = fmaf(w2, U0[idx - D_INNER], acc);
    if (l >= 2) acc = fmaf(w1, U0[idx - 2 * D_INNER], acc);
    if (l >= 3) acc = fmaf(w0, U0[idx - 3 * D_INNER], acc);
    U[idx] = acc / (1.f + expf(-acc));
}

// ---------------- chunked 2-pass SSM scan ----------------
__global__ __launch_bounds__(256)
void scan_pass1(const float* __restrict__ delta, const float* __restrict__ u,
                const float* __restrict__ A_log, const float* __restrict__ Bm,
                float* __restrict__ hS, float* __restrict__ pS)
{
    const int tid  = threadIdx.x;
    const int n    = tid & 15;
    const int dgrp = tid >> 4;
    const int bx   = blockIdx.x;
    const int d     = (bx & 127) * 16 + dgrp;
    const int chunk = bx >> 7;

    const float A  = -expf(A_log[n]);
    const float Bn = Bm[n * D_INNER + d];
    const bool  smallA = fabsf(A) < 1e-6f;
    const float invA   = smallA ? 0.f : 1.f / A;

    float h = 0.f, p = 1.f;
    size_t idx = (size_t)(chunk * CHUNK) * D_INNER + d;
    for (int l = 0; l < CHUNK; l++) {
        float dt = delta[idx];
        float uu = u[idx];
        float dA = dt * A;
        float ab = __expf(dA);
        float ex = smallA ? dt * (1.f + 0.5f * dA) : (ab - 1.f) * invA;
        h = fmaf(ab, h, ex * Bn * uu);
        p *= ab;
        idx += D_INNER;
    }
    int o = (chunk * D_INNER + d) * 16 + n;
    hS[o] = h;
    pS[o] = p;
}

__global__ __launch_bounds__(256)
void scan_mid(const float* __restrict__ hS, const float* __restrict__ pS,
              float* __restrict__ hin)
{
    int i = blockIdx.x * 256 + threadIdx.x;   // (d,n): i = d*16+n
    int d = i >> 4, n = i & 15;
    float carry = 0.f;
    #pragma unroll
    for (int c = 0; c < NCHUNK; c++) {
        int o = (c * D_INNER + d) * 16 + n;
        hin[o] = carry;
        carry = fmaf(pS[o], carry, hS[o]);
    }
}

__global__ __launch_bounds__(256)
void scan_pass2(const float* __restrict__ delta, const float* __restrict__ u,
                const float* __restrict__ gpre, const float* __restrict__ A_log,
                const float* __restrict__ Bm, const float* __restrict__ Cm,
                const float* __restrict__ Dv, const float* __restrict__ hin,
                float* __restrict__ Y)
{
    const int tid  = threadIdx.x;
    const int n    = tid & 15;
    const int dgrp = tid >> 4;
    const int bx   = blockIdx.x;
    const int d     = (bx & 127) * 16 + dgrp;
    const int chunk = bx >> 7;

    const float A  = -expf(A_log[n]);
    const float Bn = Bm[n * D_INNER + d];
    const float Cn = Cm[n * D_INNER + d];
    const float Dd = Dv[d];
    const bool  smallA = fabsf(A) < 1e-6f;
    const float invA   = smallA ? 0.f : 1.f / A;

    float h = hin[(chunk * D_INNER + d) * 16 + n];
    size_t idx = (size_t)(chunk * CHUNK) * D_INNER + d;
    for (int l = 0; l < CHUNK; l++) {
        float dt = delta[idx];
        float uu = u[idx];
        float dA = dt * A;
        float ab = __expf(dA);
        float ex = smallA ? dt * (1.f + 0.5f * dA) : (ab - 1.f) * invA;
        h = fmaf(ab, h, ex * Bn * uu);
        float c = h * Cn;
        c += __shfl_xor_sync(0xffffffffu, c, 1);
        c += __shfl_xor_sync(0xffffffffu, c, 2);
        c += __shfl_xor_sync(0xffffffffu, c, 4);
        c += __shfl_xor_sync(0xffffffffu, c, 8);
        if (n == 0) {
            float gg = gpre[idx];
            float sil = gg / (1.f + expf(-gg));
            Y[idx] = (c + Dd * uu) * sil;
        }
        idx += D_INNER;
    }
}

// ---------------- launcher ----------------
extern "C" void kernel_launch(void* const* d_in, const int* in_sizes, int n_in,
                              void* d_out, int out_size)
{
    const float* x      = (const float*)d_in[0];
    const float* in_w   = (const float*)d_in[1];
    const float* in_b   = (const float*)d_in[2];
    const float* conv_w = (const float*)d_in[3];
    const float* conv_b = (const float*)d_in[4];
    const float* A_log  = (const float*)d_in[5];
    const float* B_mat  = (const float*)d_in[6];
    const float* C_mat  = (const float*)d_in[7];
    const float* D_vec  = (const float*)d_in[8];
    const float* gate_w = (const float*)d_in[9];
    const float* gate_b = (const float*)d_in[10];
    const float* dt1_w  = (const float*)d_in[11];
    const float* dt1_b  = (const float*)d_in[12];
    const float* dt2_w  = (const float*)d_in[13];
    const float* dt2_b  = (const float*)d_in[14];
    const float* out_w  = (const float*)d_in[15];
    const float* out_b  = (const float*)d_in[16];
    float* out = (float*)d_out;

    float *u0, *gate, *u, *t, *delta, *y, *hS, *pS, *hin;
    bf16 *xA, *uA, *tA, *yA, *inB, *gateB, *dt1B, *dt2B, *outB;
    cudaGetSymbolAddress((void**)&u0, g_u0);       cudaGetSymbolAddress((void**)&gate, g_gate);
    cudaGetSymbolAddress((void**)&u, g_u);         cudaGetSymbolAddress((void**)&t, g_t);
    cudaGetSymbolAddress((void**)&delta, g_delta); cudaGetSymbolAddress((void**)&y, g_y);
    cudaGetSymbolAddress((void**)&hS, g_hS);       cudaGetSymbolAddress((void**)&pS, g_pS);
    cudaGetSymbolAddress((void**)&hin, g_hin);
    cudaGetSymbolAddress((void**)&xA, g_xA);       cudaGetSymbolAddress((void**)&uA, g_uA);
    cudaGetSymbolAddress((void**)&tA, g_tA);       cudaGetSymbolAddress((void**)&yA, g_yA);
    cudaGetSymbolAddress((void**)&inB, g_inB);     cudaGetSymbolAddress((void**)&gateB, g_gateB);
    cudaGetSymbolAddress((void**)&dt1B, g_dt1B);   cudaGetSymbolAddress((void**)&dt2B, g_dt2B);
    cudaGetSymbolAddress((void**)&outB, g_outB);

    cudaFuncSetAttribute(tgemm, cudaFuncAttributeMaxDynamicSharedMemorySize, TG_SMEM);

    // ---- weight splits (W[K,N] -> [3K,ldb]) ----
    split_w<<<(D_MODEL * D_INNER / 4 + 255) / 256, 256>>>((const float4*)in_w,   inB,
        D_INNER / 4, D_INNER, D_INNER, D_MODEL, D_MODEL * D_INNER / 4);
    split_w<<<(D_MODEL * D_INNER / 4 + 255) / 256, 256>>>((const float4*)gate_w, gateB,
        D_INNER / 4, D_INNER, D_INNER, D_MODEL, D_MODEL * D_INNER / 4);
    split_w<<<(D_INNER * DT_RANK / 4 + 255) / 256, 256>>>((const float4*)dt1_w,  dt1B,
        DT_RANK / 4, DT_RANK, 128, D_INNER, D_INNER * DT_RANK / 4);
    pad_dt1<<<(3 * D_INNER * 32 + 255) / 256, 256>>>(dt1B);
    split_w<<<(DT_RANK * D_INNER / 4 + 255) / 256, 256>>>((const float4*)dt2_w,  dt2B,
        D_INNER / 4, D_INNER, D_INNER, DT_RANK, DT_RANK * D_INNER / 4);
    split_w<<<(D_INNER * D_MODEL / 4 + 255) / 256, 256>>>((const float4*)out_w,  outB,
        D_MODEL / 4, D_MODEL, D_MODEL, D_INNER, D_INNER * D_MODEL / 4);

    // ---- x split ----
    split_act<<<(L_SEQ * D_MODEL / 4 + 255) / 256, 256>>>((const float4*)x, xA,
        D_MODEL / 4, D_MODEL, L_SEQ * D_MODEL / 4);

    // ---- in-proj + gate-proj ----
    tgemm<<<dim3(D_INNER / 128, L_SEQ / 128), 256, TG_SMEM>>>(
        xA, inB, in_b, u0, 3 * D_MODEL, D_INNER, D_INNER, 128, 0);
    tgemm<<<dim3(D_INNER / 128, L_SEQ / 128), 256, TG_SMEM>>>(
        xA, gateB, gate_b, gate, 3 * D_MODEL, D_INNER, D_INNER, 128, 0);

    // ---- conv + silu ----
    conv_silu<<<(L_SEQ * D_INNER) / 256, 256>>>(u0, conv_w, conv_b, u);

    // ---- u split + dt1 (N padded to 128, Nvalid=64) ----
    split_act<<<(L_SEQ * D_INNER / 4 + 255) / 256, 256>>>((const float4*)u, uA,
        D_INNER / 4, D_INNER, L_SEQ * D_INNER / 4);
    tgemm<<<dim3(1, L_SEQ / 128), 256, TG_SMEM>>>(
        uA, dt1B, dt1_b, t, 3 * D_INNER, 128, DT_RANK, DT_RANK, 0);

    // ---- t split + dt2 (+softplus) ----
    split_act<<<(L_SEQ * DT_RANK / 4 + 255) / 256, 256>>>((const float4*)t, tA,
        DT_RANK / 4, DT_RANK, L_SEQ * DT_RANK / 4);
    tgemm<<<dim3(D_INNER / 128, L_SEQ / 128), 256, TG_SMEM>>>(
        tA, dt2B, dt2_b, delta, 3 * DT_RANK, D_INNER, D_INNER, 128, 1);

    // ---- chunked scan ----
    scan_pass1<<<NCHUNK * (D_INNER / 16), 256>>>(delta, u, A_log, B_mat, hS, pS);
    scan_mid<<<(D_INNER * 16) / 256, 256>>>(hS, pS, hin);
    scan_pass2<<<NCHUNK * (D_INNER / 16), 256>>>(delta, u, gate, A_log, B_mat,
                                                 C_mat, D_vec, hin, y);

    // ---- y split + out-proj ----
    split_act<<<(L_SEQ * D_INNER / 4 + 255) / 256, 256>>>((const float4*)y, yA,
        D_INNER / 4, D_INNER, L_SEQ * D_INNER / 4);
    tgemm<<<dim3(D_MODEL / 128, L_SEQ / 128), 256, TG_SMEM>>>(
        yA, outB, out_b, out, 3 * D_INNER, D_MODEL, D_MODEL, 128, 0);
}

// round 5
// speedup vs baseline: 3.1559x; 1.1882x over previous
#include <cuda_runtime.h>
#include <cuda_fp16.h>
#include <math.h>

// ---------------- problem constants ----------------
#define L_SEQ   2048
#define D_MODEL 1024
#define D_INNER 2048
#define DT_RANK 64
#define NCHUNK  16
#define CHUNK   128

// ---------------- scratch (no allocations allowed) ----------------
__device__ float g_u0[L_SEQ * D_INNER];
__device__ float g_gate[L_SEQ * D_INNER];
__device__ float g_u[L_SEQ * D_INNER];
__device__ float g_t[L_SEQ * DT_RANK];
__device__ float g_delta[L_SEQ * D_INNER];

// split fp16 activations A' = [Ah | Al]  (M x 2K)
__device__ half g_xA[L_SEQ * 2 * D_MODEL];
__device__ half g_uA[L_SEQ * 2 * D_INNER];
__device__ half g_tA[L_SEQ * 2 * DT_RANK];
__device__ half g_yA[L_SEQ * 2 * D_INNER];

// fp16 weights B' = [Bh ; Bh]  (2K x ldb)  (hi duplicated)
__device__ half g_inB[2 * D_MODEL * D_INNER];
__device__ half g_gateB[2 * D_MODEL * D_INNER];
__device__ half g_dt1B[2 * D_INNER * 128];      // N padded 64 -> 128
__device__ half g_dt2B[2 * DT_RANK * D_INNER];
__device__ half g_outB[2 * D_INNER * D_MODEL];

// chunked scan state
__device__ float g_hS[NCHUNK * D_INNER * 16];
__device__ float g_pS[NCHUNK * D_INNER * 16];
__device__ float g_hin[NCHUNK * D_INNER * 16];

// ---------------- helpers ----------------
__device__ __forceinline__ unsigned smem_u32(const void* p) {
    unsigned a;
    asm("{ .reg .u64 t; cvta.to.shared.u64 t, %1; cvt.u32.u64 %0, t; }"
        : "=r"(a) : "l"(p));
    return a;
}

__device__ __forceinline__ void cp16(unsigned saddr, const void* g) {
    asm volatile("cp.async.cg.shared.global [%0], [%1], 16;"
                 :: "r"(saddr), "l"(g));
}
#define CP_COMMIT() asm volatile("cp.async.commit_group;" ::: "memory")
#define CP_WAIT(n)  asm volatile("cp.async.wait_group %0;" :: "n"(n) : "memory")

#define LDSM_X4(r, addr) \
    asm volatile("ldmatrix.sync.aligned.m8n8.x4.shared.b16 {%0,%1,%2,%3}, [%4];" \
        : "=r"((r)[0]), "=r"((r)[1]), "=r"((r)[2]), "=r"((r)[3]) : "r"(addr))

#define LDSM_X4_T(r, addr) \
    asm volatile("ldmatrix.sync.aligned.m8n8.x4.trans.shared.b16 {%0,%1,%2,%3}, [%4];" \
        : "=r"((r)[0]), "=r"((r)[1]), "=r"((r)[2]), "=r"((r)[3]) : "r"(addr))

#define MMA16816(d, a, b0, b1) \
    asm volatile("mma.sync.aligned.m16n8k16.row.col.f32.f16.f16.f32 " \
        "{%0,%1,%2,%3}, {%4,%5,%6,%7}, {%8,%9}, {%0,%1,%2,%3};" \
        : "+f"((d)[0]), "+f"((d)[1]), "+f"((d)[2]), "+f"((d)[3]) \
        : "r"((a)[0]), "r"((a)[1]), "r"((a)[2]), "r"((a)[3]), "r"(b0), "r"(b1))

// ---------------- fp16 HMMA GEMM: C[M,N] = A'[M,Kp] @ B'[Kp,N] ----------------
// tile 128x128, 8 warps (each 32x64), K chunk = 64 fp16, 2-stage cp.async.
#define TG_SMEM 65536

__global__ __launch_bounds__(256, 2)
void tgemm(const half* __restrict__ A, const half* __restrict__ B,
           const float* __restrict__ bias, float* __restrict__ C,
           int Kp, int ldb, int ldc, int Nvalid, int softplus_ep)
{
    extern __shared__ char smem[];
    const unsigned sb = smem_u32(smem);
    const int tid  = threadIdx.x;
    const int wid  = tid >> 5;
    const int lane = tid & 31;
    const int m0 = blockIdx.y * 128;
    const int n0 = blockIdx.x * 128;
    const int warp_m = (wid & 3) * 32;
    const int warp_n = (wid >> 2) * 64;

    float acc[2][8][4];
    #pragma unroll
    for (int i = 0; i < 2; i++)
        #pragma unroll
        for (int j = 0; j < 8; j++)
            #pragma unroll
            for (int q = 0; q < 4; q++) acc[i][j][q] = 0.f;

    const int nc = Kp >> 6;

    auto load_stage = [&](int c, int s) {
        unsigned st = sb + (unsigned)s * 32768u;
        int k0 = c << 6;
        #pragma unroll
        for (int i = 0; i < 4; i++) {
            int idx = i * 256 + tid;
            int r  = idx >> 3;
            int ch = idx & 7;
            cp16(st + (unsigned)(r * 128 + ((ch ^ (r & 7)) << 4)),
                 A + (size_t)(m0 + r) * Kp + k0 + ch * 8);
        }
        #pragma unroll
        for (int i = 0; i < 4; i++) {
            int idx = i * 256 + tid;
            int k  = idx >> 4;
            int ch = idx & 15;
            cp16(st + 16384u + (unsigned)(k * 256 + ((ch ^ (k & 7)) << 4)),
                 B + (size_t)(k0 + k) * ldb + n0 + ch * 8);
        }
    };

    load_stage(0, 0);
    CP_COMMIT();

    for (int c = 0; c < nc; c++) {
        if (c + 1 < nc) {
            load_stage(c + 1, (c + 1) & 1);
            CP_COMMIT();
            CP_WAIT(1);
        } else {
            CP_WAIT(0);
        }
        __syncthreads();

        unsigned sA = sb + (unsigned)(c & 1) * 32768u;
        unsigned sB = sA + 16384u;

        #pragma unroll
        for (int ks = 0; ks < 4; ks++) {
            unsigned af[2][4];
            #pragma unroll
            for (int mi = 0; mi < 2; mi++) {
                int m  = warp_m + mi * 16 + (lane & 15);
                int ch = ks * 2 + (lane >> 4);
                LDSM_X4(af[mi], sA + (unsigned)(m * 128 + ((ch ^ (m & 7)) << 4)));
            }
            unsigned bfg[4][4];
            #pragma unroll
            for (int nj2 = 0; nj2 < 4; nj2++) {
                int k  = ks * 16 + (lane & 15);
                int ch = ((warp_n + nj2 * 16) >> 3) + (lane >> 4);
                LDSM_X4_T(bfg[nj2], sB + (unsigned)(k * 256 + ((ch ^ (k & 7)) << 4)));
            }
            #pragma unroll
            for (int mi = 0; mi < 2; mi++)
                #pragma unroll
                for (int nj = 0; nj < 8; nj++)
                    MMA16816(acc[mi][nj], af[mi],
                             bfg[nj >> 1][(nj & 1) * 2], bfg[nj >> 1][(nj & 1) * 2 + 1]);
        }
        __syncthreads();
    }

    #pragma unroll
    for (int mi = 0; mi < 2; mi++) {
        int r = m0 + warp_m + mi * 16 + (lane >> 2);
        #pragma unroll
        for (int nj = 0; nj < 8; nj++) {
            int col = warp_n + nj * 8 + (lane & 3) * 2;
            if (col < Nvalid) {
                float b0 = bias[col], b1 = bias[col + 1];
                float v0 = acc[mi][nj][0] + b0, v1 = acc[mi][nj][1] + b1;
                float v2 = acc[mi][nj][2] + b0, v3 = acc[mi][nj][3] + b1;
                if (softplus_ep) {
                    v0 = (v0 > 20.f) ? v0 : log1pf(expf(v0));
                    v1 = (v1 > 20.f) ? v1 : log1pf(expf(v1));
                    v2 = (v2 > 20.f) ? v2 : log1pf(expf(v2));
                    v3 = (v3 > 20.f) ? v3 : log1pf(expf(v3));
                }
                *(float2*)(C + (size_t)r * ldc + n0 + col)       = make_float2(v0, v1);
                *(float2*)(C + (size_t)(r + 8) * ldc + n0 + col) = make_float2(v2, v3);
            }
        }
    }
}

// ---------------- split kernels ----------------
__device__ __forceinline__ void split1(float v, half& h, half& l) {
    h = __float2half_rn(v);
    l = __float2half_rn(v - __half2float(h));
}

// activations: V[M,K] fp32 -> O[M,2K] fp16 = [hi | lo]
__global__ __launch_bounds__(256)
void split_act(const float4* __restrict__ V, half* __restrict__ O,
               int K4, int K, int total4)
{
    int i = blockIdx.x * 256 + threadIdx.x;
    if (i >= total4) return;
    int m = i / K4;
    int k = (i - m * K4) * 4;
    float4 v = V[i];
    half h0, l0, h1, l1, h2, l2, h3, l3;
    split1(v.x, h0, l0); split1(v.y, h1, l1);
    split1(v.z, h2, l2); split1(v.w, h3, l3);
    half2* p0 = (half2*)(O + (size_t)m * 2 * K + k);
    half2* p1 = (half2*)(O + (size_t)m * 2 * K + K + k);
    p0[0] = half2{h0, h1}; p0[1] = half2{h2, h3};
    p1[0] = half2{l0, l1}; p1[1] = half2{l2, l3};
}

// weights: W[K,N] fp32 -> O[2K, ldb] fp16 rows = [hi ; hi]
__global__ __launch_bounds__(256)
void split_w(const float4* __restrict__ W, half* __restrict__ O,
             int N4, int N, int ldb, int K, int total4)
{
    int i = blockIdx.x * 256 + threadIdx.x;
    if (i >= total4) return;
    int k = i / N4;
    int n = (i - k * N4) * 4;
    float4 v = W[i];
    half2 h01 = {__float2half_rn(v.x), __float2half_rn(v.y)};
    half2 h23 = {__float2half_rn(v.z), __float2half_rn(v.w)};
    half2* p0 = (half2*)(O + (size_t)k * ldb + n);
    half2* p1 = (half2*)(O + (size_t)(K + k) * ldb + n);
    p0[0] = h01; p0[1] = h23;
    p1[0] = h01; p1[1] = h23;
}

// zero pad cols [64,128) of dt1B rows (2*2048 rows)
__global__ __launch_bounds__(256)
void pad_dt1(half* __restrict__ O)
{
    int i = blockIdx.x * 256 + threadIdx.x;   // over 2*2048 * 32 half2 units
    int row = i >> 5;
    int c2  = (i & 31) * 2;
    ((half2*)(O + (size_t)row * 128 + 64 + c2))[0] = half2{(half)0.f, (half)0.f};
}

// ---------------- conv(width4) + SiLU + fp16 split (fused) ----------------
__global__ __launch_bounds__(256)
void conv_silu_split(const float* __restrict__ U0, const float* __restrict__ cw,
                     const float* __restrict__ cb, float* __restrict__ U,
                     half* __restrict__ UA)
{
    int idx = blockIdx.x * blockDim.x + threadIdx.x;
    if (idx >= L_SEQ * D_INNER) return;
    int d = idx & (D_INNER - 1);
    int l = idx >> 11;
    float w0 = cw[d * 4 + 0], w1 = cw[d * 4 + 1], w2 = cw[d * 4 + 2], w3 = cw[d * 4 + 3];
    float acc = cb[d] + w3 * U0[idx];
    if (l >= 1) acc = fmaf(w2, U0[idx - D_INNER], acc);
    if (l >= 2) acc = fmaf(w1, U0[idx - 2 * D_INNER], acc);
    if (l >= 3) acc = fmaf(w0, U0[idx - 3 * D_INNER], acc);
    float s = acc / (1.f + expf(-acc));
    U[idx] = s;
    half h, lo;
    split1(s, h, lo);
    size_t base = (size_t)l * 2 * D_INNER + d;
    UA[base] = h;
    UA[base + D_INNER] = lo;
}

// ---------------- chunked 2-pass SSM scan ----------------
__global__ __launch_bounds__(256)
void scan_pass1(const float* __restrict__ delta, const float* __restrict__ u,
                const float* __restrict__ A_log, const float* __restrict__ Bm,
                float* __restrict__ hS, float* __restrict__ pS)
{
    const int tid  = threadIdx.x;
    const int n    = tid & 15;
    const int dgrp = tid >> 4;
    const int bx   = blockIdx.x;
    const int d     = (bx & 127) * 16 + dgrp;
    const int chunk = bx >> 7;

    const float A  = -expf(A_log[n]);
    const float Bn = Bm[n * D_INNER + d];
    const bool  smallA = fabsf(A) < 1e-6f;
    const float invA   = smallA ? 0.f : 1.f / A;

    float h = 0.f, p = 1.f;
    size_t idx = (size_t)(chunk * CHUNK) * D_INNER + d;
    for (int l = 0; l < CHUNK; l++) {
        float dt = delta[idx];
        float uu = u[idx];
        float dA = dt * A;
        float ab = __expf(dA);
        float ex = smallA ? dt * (1.f + 0.5f * dA) : (ab - 1.f) * invA;
        h = fmaf(ab, h, ex * Bn * uu);
        p *= ab;
        idx += D_INNER;
    }
    int o = (chunk * D_INNER + d) * 16 + n;
    hS[o] = h;
    pS[o] = p;
}

__global__ __launch_bounds__(256)
void scan_mid(const float* __restrict__ hS, const float* __restrict__ pS,
              float* __restrict__ hin)
{
    int i = blockIdx.x * 256 + threadIdx.x;
    int d = i >> 4, n = i & 15;
    float carry = 0.f;
    #pragma unroll
    for (int c = 0; c < NCHUNK; c++) {
        int o = (c * D_INNER + d) * 16 + n;
        hin[o] = carry;
        carry = fmaf(pS[o], carry, hS[o]);
    }
}

__global__ __launch_bounds__(256)
void scan_pass2(const float* __restrict__ delta, const float* __restrict__ u,
                const float* __restrict__ gpre, const float* __restrict__ A_log,
                const float* __restrict__ Bm, const float* __restrict__ Cm,
                const float* __restrict__ Dv, const float* __restrict__ hin,
                half* __restrict__ YA)
{
    const int tid  = threadIdx.x;
    const int n    = tid & 15;
    const int dgrp = tid >> 4;
    const int bx   = blockIdx.x;
    const int d     = (bx & 127) * 16 + dgrp;
    const int chunk = bx >> 7;

    const float A  = -expf(A_log[n]);
    const float Bn = Bm[n * D_INNER + d];
    const float Cn = Cm[n * D_INNER + d];
    const float Dd = Dv[d];
    const bool  smallA = fabsf(A) < 1e-6f;
    const float invA   = smallA ? 0.f : 1.f / A;

    float h = hin[(chunk * D_INNER + d) * 16 + n];
    size_t idx = (size_t)(chunk * CHUNK) * D_INNER + d;
    size_t ybase = (size_t)(chunk * CHUNK) * 2 * D_INNER + d;
    for (int l = 0; l < CHUNK; l++) {
        float dt = delta[idx];
        float uu = u[idx];
        float dA = dt * A;
        float ab = __expf(dA);
        float ex = smallA ? dt * (1.f + 0.5f * dA) : (ab - 1.f) * invA;
        h = fmaf(ab, h, ex * Bn * uu);
        float c = h * Cn;
        c += __shfl_xor_sync(0xffffffffu, c, 1);
        c += __shfl_xor_sync(0xffffffffu, c, 2);
        c += __shfl_xor_sync(0xffffffffu, c, 4);
        c += __shfl_xor_sync(0xffffffffu, c, 8);
        if (n == 0) {
            float gg = gpre[idx];
            float sil = gg / (1.f + expf(-gg));
            float val = (c + Dd * uu) * sil;
            half hh, ll;
            split1(val, hh, ll);
            YA[ybase] = hh;
            YA[ybase + D_INNER] = ll;
        }
        idx += D_INNER;
        ybase += 2 * D_INNER;
    }
}

// ---------------- launcher ----------------
extern "C" void kernel_launch(void* const* d_in, const int* in_sizes, int n_in,
                              void* d_out, int out_size)
{
    const float* x      = (const float*)d_in[0];
    const float* in_w   = (const float*)d_in[1];
    const float* in_b   = (const float*)d_in[2];
    const float* conv_w = (const float*)d_in[3];
    const float* conv_b = (const float*)d_in[4];
    const float* A_log  = (const float*)d_in[5];
    const float* B_mat  = (const float*)d_in[6];
    const float* C_mat  = (const float*)d_in[7];
    const float* D_vec  = (const float*)d_in[8];
    const float* gate_w = (const float*)d_in[9];
    const float* gate_b = (const float*)d_in[10];
    const float* dt1_w  = (const float*)d_in[11];
    const float* dt1_b  = (const float*)d_in[12];
    const float* dt2_w  = (const float*)d_in[13];
    const float* dt2_b  = (const float*)d_in[14];
    const float* out_w  = (const float*)d_in[15];
    const float* out_b  = (const float*)d_in[16];
    float* out = (float*)d_out;

    float *u0, *gate, *u, *t, *delta, *hS, *pS, *hin;
    half *xA, *uA, *tA, *yA, *inB, *gateB, *dt1B, *dt2B, *outB;
    cudaGetSymbolAddress((void**)&u0, g_u0);       cudaGetSymbolAddress((void**)&gate, g_gate);
    cudaGetSymbolAddress((void**)&u, g_u);         cudaGetSymbolAddress((void**)&t, g_t);
    cudaGetSymbolAddress((void**)&delta, g_delta);
    cudaGetSymbolAddress((void**)&hS, g_hS);       cudaGetSymbolAddress((void**)&pS, g_pS);
    cudaGetSymbolAddress((void**)&hin, g_hin);
    cudaGetSymbolAddress((void**)&xA, g_xA);       cudaGetSymbolAddress((void**)&uA, g_uA);
    cudaGetSymbolAddress((void**)&tA, g_tA);       cudaGetSymbolAddress((void**)&yA, g_yA);
    cudaGetSymbolAddress((void**)&inB, g_inB);     cudaGetSymbolAddress((void**)&gateB, g_gateB);
    cudaGetSymbolAddress((void**)&dt1B, g_dt1B);   cudaGetSymbolAddress((void**)&dt2B, g_dt2B);
    cudaGetSymbolAddress((void**)&outB, g_outB);

    cudaFuncSetAttribute(tgemm, cudaFuncAttributeMaxDynamicSharedMemorySize, TG_SMEM);

    // ---- weight splits (W[K,N] -> [2K,ldb], hi duplicated) ----
    split_w<<<(D_MODEL * D_INNER / 4 + 255) / 256, 256>>>((const float4*)in_w,   inB,
        D_INNER / 4, D_INNER, D_INNER, D_MODEL, D_MODEL * D_INNER / 4);
    split_w<<<(D_MODEL * D_INNER / 4 + 255) / 256, 256>>>((const float4*)gate_w, gateB,
        D_INNER / 4, D_INNER, D_INNER, D_MODEL, D_MODEL * D_INNER / 4);
    split_w<<<(D_INNER * DT_RANK / 4 + 255) / 256, 256>>>((const float4*)dt1_w,  dt1B,
        DT_RANK / 4, DT_RANK, 128, D_INNER, D_INNER * DT_RANK / 4);
    pad_dt1<<<(2 * D_INNER * 32 + 255) / 256, 256>>>(dt1B);
    split_w<<<(DT_RANK * D_INNER / 4 + 255) / 256, 256>>>((const float4*)dt2_w,  dt2B,
        D_INNER / 4, D_INNER, D_INNER, DT_RANK, DT_RANK * D_INNER / 4);
    split_w<<<(D_INNER * D_MODEL / 4 + 255) / 256, 256>>>((const float4*)out_w,  outB,
        D_MODEL / 4, D_MODEL, D_MODEL, D_INNER, D_INNER * D_MODEL / 4);

    // ---- x split ----
    split_act<<<(L_SEQ * D_MODEL / 4 + 255) / 256, 256>>>((const float4*)x, xA,
        D_MODEL / 4, D_MODEL, L_SEQ * D_MODEL / 4);

    // ---- in-proj + gate-proj (Kp = 2*1024) ----
    tgemm<<<dim3(D_INNER / 128, L_SEQ / 128), 256, TG_SMEM>>>(
        xA, inB, in_b, u0, 2 * D_MODEL, D_INNER, D_INNER, 128, 0);
    tgemm<<<dim3(D_INNER / 128, L_SEQ / 128), 256, TG_SMEM>>>(
        xA, gateB, gate_b, gate, 2 * D_MODEL, D_INNER, D_INNER, 128, 0);

    // ---- conv + silu + split (fused) ----
    conv_silu_split<<<(L_SEQ * D_INNER) / 256, 256>>>(u0, conv_w, conv_b, u, uA);

    // ---- dt1 (Kp = 2*2048, N padded to 128, Nvalid=64) ----
    tgemm<<<dim3(1, L_SEQ / 128), 256, TG_SMEM>>>(
        uA, dt1B, dt1_b, t, 2 * D_INNER, 128, DT_RANK, DT_RANK, 0);

    // ---- t split + dt2 (+softplus, Kp = 2*64) ----
    split_act<<<(L_SEQ * DT_RANK / 4 + 255) / 256, 256>>>((const float4*)t, tA,
        DT_RANK / 4, DT_RANK, L_SEQ * DT_RANK / 4);
    tgemm<<<dim3(D_INNER / 128, L_SEQ / 128), 256, TG_SMEM>>>(
        tA, dt2B, dt2_b, delta, 2 * DT_RANK, D_INNER, D_INNER, 128, 1);

    // ---- chunked scan (pass2 emits fp16 split y directly) ----
    scan_pass1<<<NCHUNK * (D_INNER / 16), 256>>>(delta, u, A_log, B_mat, hS, pS);
    scan_mid<<<(D_INNER * 16) / 256, 256>>>(hS, pS, hin);
    scan_pass2<<<NCHUNK * (D_INNER / 16), 256>>>(delta, u, gate, A_log, B_mat,
                                                 C_mat, D_vec, hin, yA);

    // ---- out-proj (Kp = 2*2048) ----
    tgemm<<<dim3(D_MODEL / 128, L_SEQ / 128), 256, TG_SMEM>>>(
        yA, outB, out_b, out, 2 * D_INNER, D_MODEL, D_MODEL, 128, 0);
}